// round 1
// baseline (speedup 1.0000x reference)
#include <cuda_runtime.h>
#include <cuda_bf16.h>
#include <cstdint>

// ---------------------------------------------------------------------------
// MistralQuantizedMLP: out = (silu(x@Wg^T*sg) * (x@Wu^T*su)) @ Wd^T * sd
// Weights are int8-valued -> exact in bf16 with scale folded into epilogue.
// Activations split hi/lo bf16 so the double-GEMM is ~fp32-exact.
// ---------------------------------------------------------------------------

static constexpr int MDIM = 4096;   // B*S
static constexpr int HDIM = 4096;
static constexpr int IDIM = 14336;

static constexpr int BM = 128, BN = 128, BK = 32;
static constexpr int LDT = BK + 8;                 // 40 elems = 80B pitch (16B-aligned, conflict-free)
static constexpr int BUF_ELEMS = 3 * BM * LDT;     // [A_hi | A_lo | B] per stage
static constexpr int SMEM_BYTES = 2 * BUF_ELEMS * (int)sizeof(__nv_bfloat16);  // 61440

// ---- static device scratch (allocation-free rule) ----
__device__ __nv_bfloat16 g_wg[(size_t)IDIM * HDIM];
__device__ __nv_bfloat16 g_wu[(size_t)IDIM * HDIM];
__device__ __nv_bfloat16 g_wd[(size_t)HDIM * IDIM];
__device__ __nv_bfloat16 g_xhi[(size_t)MDIM * HDIM];
__device__ __nv_bfloat16 g_xlo[(size_t)MDIM * HDIM];
__device__ float         g_gate[(size_t)MDIM * IDIM];
__device__ float         g_up[(size_t)MDIM * IDIM];
__device__ __nv_bfloat16 g_hhi[(size_t)MDIM * IDIM];
__device__ __nv_bfloat16 g_hlo[(size_t)MDIM * IDIM];

// ---------------------------------------------------------------------------
// Elementwise kernels
// ---------------------------------------------------------------------------
__global__ void k_convert_w(const int4* __restrict__ wq,
                            __nv_bfloat162* __restrict__ out, int n4) {
    int i = blockIdx.x * blockDim.x + threadIdx.x;
    int stride = gridDim.x * blockDim.x;
    for (; i < n4; i += stride) {
        int4 v = wq[i];
        out[2 * i + 0] = __halves2bfloat162(__float2bfloat16_rn((float)v.x),
                                            __float2bfloat16_rn((float)v.y));
        out[2 * i + 1] = __halves2bfloat162(__float2bfloat16_rn((float)v.z),
                                            __float2bfloat16_rn((float)v.w));
    }
}

__device__ __forceinline__ void split1(float v, __nv_bfloat16& h, __nv_bfloat16& l) {
    h = __float2bfloat16_rn(v);
    l = __float2bfloat16_rn(v - __bfloat162float(h));
}

__global__ void k_split_x(const float4* __restrict__ x,
                          __nv_bfloat162* __restrict__ hi,
                          __nv_bfloat162* __restrict__ lo, int n4) {
    int i = blockIdx.x * blockDim.x + threadIdx.x;
    int stride = gridDim.x * blockDim.x;
    for (; i < n4; i += stride) {
        float4 v = x[i];
        __nv_bfloat16 h0, l0, h1, l1, h2, l2, h3, l3;
        split1(v.x, h0, l0); split1(v.y, h1, l1);
        split1(v.z, h2, l2); split1(v.w, h3, l3);
        hi[2 * i + 0] = __halves2bfloat162(h0, h1);
        hi[2 * i + 1] = __halves2bfloat162(h2, h3);
        lo[2 * i + 0] = __halves2bfloat162(l0, l1);
        lo[2 * i + 1] = __halves2bfloat162(l2, l3);
    }
}

__device__ __forceinline__ float silu_f(float g) {
    return g / (1.0f + expf(-g));
}

__global__ void k_swiglu(const float4* __restrict__ gate,
                         const float4* __restrict__ up,
                         __nv_bfloat162* __restrict__ hhi,
                         __nv_bfloat162* __restrict__ hlo, int n4) {
    int i = blockIdx.x * blockDim.x + threadIdx.x;
    int stride = gridDim.x * blockDim.x;
    for (; i < n4; i += stride) {
        float4 g = gate[i];
        float4 u = up[i];
        float4 h;
        h.x = silu_f(g.x) * u.x;
        h.y = silu_f(g.y) * u.y;
        h.z = silu_f(g.z) * u.z;
        h.w = silu_f(g.w) * u.w;
        __nv_bfloat16 a0, b0, a1, b1, a2, b2, a3, b3;
        split1(h.x, a0, b0); split1(h.y, a1, b1);
        split1(h.z, a2, b2); split1(h.w, a3, b3);
        hhi[2 * i + 0] = __halves2bfloat162(a0, a1);
        hhi[2 * i + 1] = __halves2bfloat162(a2, a3);
        hlo[2 * i + 0] = __halves2bfloat162(b0, b1);
        hlo[2 * i + 1] = __halves2bfloat162(b2, b3);
    }
}

// ---------------------------------------------------------------------------
// GEMM: C[m,n] = scale[n] * sum_k (Ahi[m,k]+Alo[m,k]) * B[n,k]
// A,B row-major bf16 (both K-contiguous -> TN GEMM, mma row.col).
// ---------------------------------------------------------------------------
__device__ __forceinline__ void cp_async16(void* sdst, const void* gsrc) {
    uint32_t s = (uint32_t)__cvta_generic_to_shared(sdst);
    asm volatile("cp.async.cg.shared.global [%0], [%1], 16;" :: "r"(s), "l"(gsrc));
}

__device__ __forceinline__ void ldm_x4(uint32_t* a, uint32_t addr) {
    asm volatile("ldmatrix.sync.aligned.m8n8.x4.shared.b16 {%0,%1,%2,%3}, [%4];"
                 : "=r"(a[0]), "=r"(a[1]), "=r"(a[2]), "=r"(a[3]) : "r"(addr));
}
__device__ __forceinline__ void ldm_x2(uint32_t* b, uint32_t addr) {
    asm volatile("ldmatrix.sync.aligned.m8n8.x2.shared.b16 {%0,%1}, [%2];"
                 : "=r"(b[0]), "=r"(b[1]) : "r"(addr));
}
__device__ __forceinline__ void mma16816(float* c, const uint32_t* a, const uint32_t* b) {
    asm volatile("mma.sync.aligned.m16n8k16.row.col.f32.bf16.bf16.f32 "
                 "{%0,%1,%2,%3}, {%4,%5,%6,%7}, {%8,%9}, {%0,%1,%2,%3};"
                 : "+f"(c[0]), "+f"(c[1]), "+f"(c[2]), "+f"(c[3])
                 : "r"(a[0]), "r"(a[1]), "r"(a[2]), "r"(a[3]), "r"(b[0]), "r"(b[1]));
}

__device__ __forceinline__ void load_stage(__nv_bfloat16* sb,
                                           const __nv_bfloat16* gA0,
                                           const __nv_bfloat16* gA1,
                                           const __nv_bfloat16* gB,
                                           int K, int k0, int tid) {
    // 1536 x 16B chunks: A_hi (512), A_lo (512), B (512); 6 per thread.
    #pragma unroll
    for (int c = tid; c < 1536; c += 256) {
        int mat = c >> 9;
        int r = (c & 511) >> 2;
        int c8 = c & 3;
        const __nv_bfloat16* src =
            (mat == 0 ? gA0 : (mat == 1 ? gA1 : gB)) + (size_t)r * K + k0 + c8 * 8;
        cp_async16(sb + (mat * BM + r) * LDT + c8 * 8, src);
    }
    asm volatile("cp.async.commit_group;" ::: "memory");
}

__global__ __launch_bounds__(256, 2)
void k_gemm(const __nv_bfloat16* __restrict__ Ahi,
            const __nv_bfloat16* __restrict__ Alo,
            const __nv_bfloat16* __restrict__ Bw,
            const float* __restrict__ scale,
            float* __restrict__ C,
            int N, int K) {
    extern __shared__ __align__(16) __nv_bfloat16 smem[];

    const int tid  = threadIdx.x;
    const int lane = tid & 31;
    const int wid  = tid >> 5;
    const int warp_m = wid >> 2;   // 0..1 -> 64 rows each
    const int warp_n = wid & 3;    // 0..3 -> 32 cols each
    const int bm = blockIdx.x * BM;
    const int bn = blockIdx.y * BN;

    const __nv_bfloat16* gA0 = Ahi + (size_t)bm * K;
    const __nv_bfloat16* gA1 = Alo + (size_t)bm * K;
    const __nv_bfloat16* gB  = Bw  + (size_t)bn * K;

    float acc[4][4][4];
    #pragma unroll
    for (int i = 0; i < 4; i++)
        #pragma unroll
        for (int j = 0; j < 4; j++)
            #pragma unroll
            for (int r = 0; r < 4; r++) acc[i][j][r] = 0.0f;

    const int KT = K / BK;
    load_stage(smem, gA0, gA1, gB, K, 0, tid);

    int buf = 0;
    for (int kt = 0; kt < KT; ++kt) {
        asm volatile("cp.async.wait_group 0;" ::: "memory");
        __syncthreads();
        if (kt + 1 < KT)
            load_stage(smem + (buf ^ 1) * BUF_ELEMS, gA0, gA1, gB, K, (kt + 1) * BK, tid);

        const __nv_bfloat16* s = smem + buf * BUF_ELEMS;
        uint32_t sA0 = (uint32_t)__cvta_generic_to_shared(s);
        uint32_t sB0 = sA0 + 2u * BM * LDT * 2u;   // byte offset past A_hi + A_lo

        #pragma unroll
        for (int ks = 0; ks < 2; ++ks) {
            uint32_t bfrag[4][2];
            #pragma unroll
            for (int ni = 0; ni < 4; ++ni) {
                int nrow = warp_n * 32 + ni * 8 + (lane & 7);
                int kcol = ks * 16 + 8 * ((lane >> 3) & 1);
                ldm_x2(bfrag[ni], sB0 + (uint32_t)(nrow * LDT + kcol) * 2u);
            }
            #pragma unroll
            for (int sel = 0; sel < 2; ++sel) {
                #pragma unroll
                for (int mi = 0; mi < 4; ++mi) {
                    int mrow = warp_m * 64 + mi * 16 + (lane & 7) + 8 * ((lane >> 3) & 1);
                    int kcol = ks * 16 + 8 * (lane >> 4);
                    uint32_t a[4];
                    ldm_x4(a, sA0 + (uint32_t)(sel * BM * LDT + mrow * LDT + kcol) * 2u);
                    #pragma unroll
                    for (int ni = 0; ni < 4; ++ni)
                        mma16816(acc[mi][ni], a, bfrag[ni]);
                }
            }
        }
        buf ^= 1;
    }

    // Epilogue: apply per-output-channel scale, write fp32.
    const int rb = bm + warp_m * 64;
    const int cb = bn + warp_n * 32;
    #pragma unroll
    for (int mi = 0; mi < 4; ++mi) {
        int r0 = rb + mi * 16 + (lane >> 2);
        #pragma unroll
        for (int ni = 0; ni < 4; ++ni) {
            int c0 = cb + ni * 8 + (lane & 3) * 2;
            float s0 = __ldg(scale + c0);
            float s1 = __ldg(scale + c0 + 1);
            float2 v0 = make_float2(acc[mi][ni][0] * s0, acc[mi][ni][1] * s1);
            float2 v1 = make_float2(acc[mi][ni][2] * s0, acc[mi][ni][3] * s1);
            *reinterpret_cast<float2*>(C + (size_t)r0 * N + c0) = v0;
            *reinterpret_cast<float2*>(C + (size_t)(r0 + 8) * N + c0) = v1;
        }
    }
}

// ---------------------------------------------------------------------------
// Launch
// ---------------------------------------------------------------------------
extern "C" void kernel_launch(void* const* d_in, const int* in_sizes, int n_in,
                              void* d_out, int out_size) {
    const float* x   = (const float*)d_in[0];
    const int*   gwq = (const int*)  d_in[1];
    const float* gsc = (const float*)d_in[2];
    const int*   uwq = (const int*)  d_in[3];
    const float* usc = (const float*)d_in[4];
    const int*   dwq = (const int*)  d_in[5];
    const float* dsc = (const float*)d_in[6];
    float* out = (float*)d_out;

    cudaFuncSetAttribute(k_gemm, cudaFuncAttributeMaxDynamicSharedMemorySize, SMEM_BYTES);

    __nv_bfloat16 *wg, *wu, *wd, *xhi, *xlo, *hhi, *hlo;
    float *gate, *up;
    cudaGetSymbolAddress((void**)&wg,  g_wg);
    cudaGetSymbolAddress((void**)&wu,  g_wu);
    cudaGetSymbolAddress((void**)&wd,  g_wd);
    cudaGetSymbolAddress((void**)&xhi, g_xhi);
    cudaGetSymbolAddress((void**)&xlo, g_xlo);
    cudaGetSymbolAddress((void**)&hhi, g_hhi);
    cudaGetSymbolAddress((void**)&hlo, g_hlo);
    cudaGetSymbolAddress((void**)&gate, g_gate);
    cudaGetSymbolAddress((void**)&up,   g_up);

    const int CT = 256;
    {
        int n4 = IDIM * HDIM / 4;
        k_convert_w<<<4096, CT>>>((const int4*)gwq, (__nv_bfloat162*)wg, n4);
        k_convert_w<<<4096, CT>>>((const int4*)uwq, (__nv_bfloat162*)wu, n4);
        k_convert_w<<<4096, CT>>>((const int4*)dwq, (__nv_bfloat162*)wd, n4);
    }
    k_split_x<<<4096, CT>>>((const float4*)x, (__nv_bfloat162*)xhi,
                            (__nv_bfloat162*)xlo, MDIM * HDIM / 4);

    dim3 grid1(MDIM / BM, IDIM / BN);   // x fastest -> weight-column L2 reuse
    k_gemm<<<grid1, 256, SMEM_BYTES>>>(xhi, xlo, wg, gsc, gate, IDIM, HDIM);
    k_gemm<<<grid1, 256, SMEM_BYTES>>>(xhi, xlo, wu, usc, up,   IDIM, HDIM);

    k_swiglu<<<8192, CT>>>((const float4*)gate, (const float4*)up,
                           (__nv_bfloat162*)hhi, (__nv_bfloat162*)hlo,
                           MDIM * IDIM / 4);

    dim3 grid2(MDIM / BM, HDIM / BN);
    k_gemm<<<grid2, 256, SMEM_BYTES>>>(hhi, hlo, wd, dsc, out, HDIM, IDIM);
}